// round 6
// baseline (speedup 1.0000x reference)
#include <cuda_runtime.h>
#include <math.h>

// Problem constants
#define BB 256
#define TT 2048
#define EE 128
#define WIN 5
#define PADW 2
#define OCC 128

// Tiling
#define CHUNK 256              // t-range per CTA
#define KCH (TT / CHUNK)       // 8 chunks per batch row
#define TILE 32                // t's per inner tile
#define NT (CHUNK / TILE)      // 8 tiles per chunk
#define ROWS (TILE + WIN - 1)  // 36 rows incl. halo
#define RST 132                // smem row stride (floats), 16B-aligned, conflict-free broadcast

// Scratch for per-(b,chunk) partial maxes: 256*8*128 floats = 1 MB (static device global — no allocs)
__device__ float g_partial[BB * KCH * OCC];

__device__ __forceinline__ unsigned long long ffma2(unsigned long long a,
                                                    unsigned long long b,
                                                    unsigned long long c) {
    unsigned long long d;
    asm("fma.rn.f32x2 %0, %1, %2, %3;" : "=l"(d) : "l"(a), "l"(b), "l"(c));
    return d;
}

__device__ __forceinline__ float2 unpack2(unsigned long long v) {
    float2 r;
    asm("mov.b64 {%0, %1}, %2;" : "=f"(r.x), "=f"(r.y) : "l"(v));
    return r;
}

__global__ void __launch_bounds__(128, 2) local_attn_main(
    const int* __restrict__ x,          // [B, T]
    const float* __restrict__ emb,      // [VOCAB+1, E]
    const float* __restrict__ attw,     // [WIN, E]
    const float* __restrict__ attb,     // [1]
    const float* __restrict__ cnnw)     // [OC, E]
{
    __shared__ float sm_emb[ROWS * RST];   // 36 x 132 floats = 19 KB
    __shared__ float sm_attw[WIN * EE];    // 2.5 KB
    __shared__ float sm_sig[TILE];

    const int tid  = threadIdx.x;
    const int warp = tid >> 5;
    const int lane = tid & 31;

    const int b      = blockIdx.x / KCH;
    const int chunk  = blockIdx.x % KCH;
    const int tchunk = chunk * CHUNK;

    // att_w -> smem (5 rows of 128)
#pragma unroll
    for (int k = 0; k < WIN; k++)
        sm_attw[k * EE + tid] = attw[k * EE + tid];
    const float att_bias = attb[0];

    // Preload this thread's cnn_w row (o = tid) into 64 packed f32x2 registers
    unsigned long long wreg[64];
    {
        const ulonglong2* wp = reinterpret_cast<const ulonglong2*>(cnnw + (size_t)tid * EE);
#pragma unroll
        for (int j = 0; j < 32; j++) {
            ulonglong2 v = wp[j];
            wreg[2 * j]     = v.x;   // floats (4j, 4j+1)
            wreg[2 * j + 1] = v.y;   // floats (4j+2, 4j+3)
        }
    }

    float vmax = -INFINITY;

    for (int tile = 0; tile < NT; tile++) {
        const int tbase = tchunk + tile * TILE;

        __syncthreads();  // previous tile's readers done before overwrite

        // ---- Stage 1: gather 36 embed rows (32 t's + 4 halo) into smem ----
        // warp w loads rows w, w+4, ..., w+32 (9 rows). Each lane: one float4.
#pragma unroll
        for (int rr = 0; rr < 9; rr++) {
            const int r  = warp + 4 * rr;
            const int tg = tbase - PADW + r;
            float4 v = make_float4(0.f, 0.f, 0.f, 0.f);
            if (tg >= 0 && tg < TT) {
                const int tok = x[b * TT + tg];  // broadcast load per warp
                v = reinterpret_cast<const float4*>(emb + (size_t)tok * EE)[lane];
            }
            reinterpret_cast<float4*>(&sm_emb[r * RST])[lane] = v;
        }
        __syncthreads();

        // ---- Stage 2: window scores + sigmoid (warp per 8 t's) ----
#pragma unroll
        for (int i = 0; i < 8; i++) {
            const int tl = warp * 8 + i;
            float c = 0.f;
#pragma unroll
            for (int j = 0; j < 4; j++) {
                const int e = lane + 32 * j;
#pragma unroll
                for (int k = 0; k < WIN; k++)
                    c += sm_emb[(tl + k) * RST + e] * sm_attw[k * EE + e];
            }
#pragma unroll
            for (int off = 16; off; off >>= 1)
                c += __shfl_xor_sync(0xffffffffu, c, off);
            if (lane == 0)
                sm_sig[tl] = 1.f / (1.f + __expf(-(c + att_bias)));
        }
        __syncthreads();

        // ---- Stage 3: per-t dot with cnn_w row (f32x2 FMAs), scale by sigma, max ----
        for (int tl = 0; tl < TILE; tl++) {
            const ulonglong2* gp =
                reinterpret_cast<const ulonglong2*>(&sm_emb[(tl + PADW) * RST]);
            unsigned long long a0 = 0ull, a1 = 0ull, a2 = 0ull, a3 = 0ull;
#pragma unroll
            for (int j = 0; j < 32; j += 2) {
                ulonglong2 g0 = gp[j];       // broadcast LDS.128
                ulonglong2 g1 = gp[j + 1];
                a0 = ffma2(g0.x, wreg[2 * j],     a0);
                a1 = ffma2(g0.y, wreg[2 * j + 1], a1);
                a2 = ffma2(g1.x, wreg[2 * j + 2], a2);
                a3 = ffma2(g1.y, wreg[2 * j + 3], a3);
            }
            float2 f0 = unpack2(a0), f1 = unpack2(a1);
            float2 f2 = unpack2(a2), f3 = unpack2(a3);
            const float d = ((f0.x + f0.y) + (f1.x + f1.y)) +
                            ((f2.x + f2.y) + (f3.x + f3.y));
            const float val = sm_sig[tl] * d;
            vmax = fmaxf(vmax, val);
        }
    }

    g_partial[(b * KCH + chunk) * OCC + tid] = vmax;
}

__global__ void local_attn_finalize(const float* __restrict__ cnnb,
                                    float* __restrict__ out) {
    const int i = blockIdx.x * blockDim.x + threadIdx.x;  // 0 .. B*OC-1
    const int b = i / OCC;
    const int o = i % OCC;
    float m = -INFINITY;
#pragma unroll
    for (int k = 0; k < KCH; k++)
        m = fmaxf(m, g_partial[(b * KCH + k) * OCC + o]);
    out[i] = tanhf(m + cnnb[o]);
}

extern "C" void kernel_launch(void* const* d_in, const int* in_sizes, int n_in,
                              void* d_out, int out_size) {
    const int*   x    = (const int*)d_in[0];
    const float* emb  = (const float*)d_in[1];
    const float* attw = (const float*)d_in[2];
    const float* attb = (const float*)d_in[3];
    const float* cnnw = (const float*)d_in[4];
    const float* cnnb = (const float*)d_in[5];
    float*       out  = (float*)d_out;   // [B, OC, 1, 1] = 32768 floats

    local_attn_main<<<BB * KCH, 128>>>(x, emb, attw, attb, cnnw);
    local_attn_finalize<<<(BB * OCC) / 256, 256>>>(cnnb, out);
}

// round 8
// speedup vs baseline: 2.6667x; 2.6667x over previous
#include <cuda_runtime.h>
#include <math.h>
#include <stdint.h>

#define BB 256
#define TT 2048
#define EE 128
#define OCC 128
#define NTILES 4096          // BB * TT / 128
#define GRID 148
#define RST 132              // padded row stride in floats (conflict-free fragment loads)

// SMEM float-index offsets
#define F_E    0                       // E tile: 128 x 132
#define F_W    (128 * RST)             // W tile: 128 x 132
#define F_ATTW (2 * 128 * RST)         // 5 x 128
#define F_Q    (F_ATTW + 5 * EE)       // 132 rows x 5 (stride 5)
#define F_SIG  (F_Q + 132 * 5)         // 128
#define SM_FLOATS (F_SIG + 128)
#define SMEM_DYN (SM_FLOATS * 4)

// per-(tile, mh) partial maxes: 4096 * 2 * 128 floats = 4 MB static scratch
__device__ float g_part[NTILES * 2 * OCC];

static __device__ __forceinline__ unsigned long long ffma2(unsigned long long a,
                                                           unsigned long long b,
                                                           unsigned long long c) {
    unsigned long long d;
    asm("fma.rn.f32x2 %0, %1, %2, %3;" : "=l"(d) : "l"(a), "l"(b), "l"(c));
    return d;
}
static __device__ __forceinline__ float2 unpack2(unsigned long long v) {
    float2 r;
    asm("mov.b64 {%0, %1}, %2;" : "=f"(r.x), "=f"(r.y) : "l"(v));
    return r;
}
static __device__ __forceinline__ unsigned long long pack2(float lo, float hi) {
    unsigned long long v;
    asm("mov.b64 %0, {%1, %2};" : "=l"(v) : "f"(lo), "f"(hi));
    return v;
}
static __device__ __forceinline__ float4 tf32x4(float4 v) {
    uint32_t a, b, c, d;
    asm("cvt.rna.tf32.f32 %0, %1;" : "=r"(a) : "f"(v.x));
    asm("cvt.rna.tf32.f32 %0, %1;" : "=r"(b) : "f"(v.y));
    asm("cvt.rna.tf32.f32 %0, %1;" : "=r"(c) : "f"(v.z));
    asm("cvt.rna.tf32.f32 %0, %1;" : "=r"(d) : "f"(v.w));
    return make_float4(__uint_as_float(a), __uint_as_float(b),
                       __uint_as_float(c), __uint_as_float(d));
}
// m16n8k8 tf32 MMA: D[t(m), o(n)], A row-major, B col-major
static __device__ __forceinline__ void mma8(float* c,
                                            uint32_t a0, uint32_t a1, uint32_t a2, uint32_t a3,
                                            uint32_t b0, uint32_t b1) {
    asm volatile(
        "mma.sync.aligned.m16n8k8.row.col.f32.tf32.tf32.f32 "
        "{%0,%1,%2,%3}, {%4,%5,%6,%7}, {%8,%9}, {%0,%1,%2,%3};"
        : "+f"(c[0]), "+f"(c[1]), "+f"(c[2]), "+f"(c[3])
        : "r"(a0), "r"(a1), "r"(a2), "r"(a3), "r"(b0), "r"(b1));
}

__global__ void __launch_bounds__(256, 1) la_main(
    const int* __restrict__ x, const float* __restrict__ emb,
    const float* __restrict__ attw, const float* __restrict__ attb,
    const float* __restrict__ cnnw)
{
    extern __shared__ float sm[];
    float* smE   = sm + F_E;
    float* smW   = sm + F_W;
    float* smATT = sm + F_ATTW;
    float* smQ   = sm + F_Q;
    float* smSIG = sm + F_SIG;

    const int tid  = threadIdx.x;
    const int lane = tid & 31;
    const int w    = tid >> 5;
    const int wo   = w & 3;          // o-quadrant (32 o's)
    const int mh   = w >> 2;         // t-half (64 t's)
    const int l4   = lane >> 2;
    const int lm   = lane & 3;
    const int r    = tid >> 1;       // row owned in gather (2 threads/row)
    const int h    = tid & 1;        // which 64-element half

    // ---- one-time init: W tile (tf32-rounded, row-major stride 132), att_w ----
    {
        const float4* src = (const float4*)(cnnw + r * EE + h * 64);
        float* dst = smW + r * RST + h * 64;
        #pragma unroll
        for (int i = 0; i < 16; i++) {
            float4 v = tf32x4(src[i]);
            *(float4*)(dst + 4 * i) = v;
        }
    }
    for (int i = tid; i < 5 * EE; i += 256) smATT[i] = attw[i];
    const float bias = attb[0];
    __syncthreads();

    const uint32_t* wE = (const uint32_t*)smE;
    const uint32_t* wW = (const uint32_t*)smW;
    const int aBase = (mh * 64 + l4) * RST + lm;
    const int bBase = (wo * 32 + l4) * RST + lm;

    for (int tile = blockIdx.x; tile < NTILES; tile += GRID) {
        const int b  = tile >> 4;
        const int tb = (tile & 15) << 7;

        __syncthreads();   // prior tile fully consumed before E overwrite

        // ---- gather E rows + in-register window-dot partials ----
        {
            const int tok = x[b * TT + tb + r];
            const float4* src = (const float4*)(emb + (size_t)tok * EE + h * 64);
            float* dst = smE + r * RST + h * 64;
            const float* aw = smATT + h * 64;
            unsigned long long a2k[5] = {0ull, 0ull, 0ull, 0ull, 0ull};
            #pragma unroll
            for (int i = 0; i < 16; i++) {
                float4 v = tf32x4(src[i]);
                *(float4*)(dst + 4 * i) = v;
                unsigned long long p01 = pack2(v.x, v.y);
                unsigned long long p23 = pack2(v.z, v.w);
                #pragma unroll
                for (int k = 0; k < 5; k++) {
                    unsigned long long w01 = *(const unsigned long long*)(aw + k * EE + 4 * i);
                    unsigned long long w23 = *(const unsigned long long*)(aw + k * EE + 4 * i + 2);
                    a2k[k] = ffma2(p01, w01, a2k[k]);
                    a2k[k] = ffma2(p23, w23, a2k[k]);
                }
            }
            float qv[5];
            #pragma unroll
            for (int k = 0; k < 5; k++) {
                float2 f = unpack2(a2k[k]);
                float s = f.x + f.y;
                s += __shfl_xor_sync(0xffffffffu, s, 1);   // combine the two row-halves
                qv[k] = s;
            }
            if (h == 0) {
                float* q = smQ + (r + 2) * 5;
                #pragma unroll
                for (int k = 0; k < 5; k++) q[k] = qv[k];
            }
        }
        // halo rows (t-2, t-1, t+128, t+129) — warp 0, 8 threads per row
        if (tid < 32) {
            const int hh = tid >> 3, seg = tid & 7;
            const int tg = (hh < 2) ? (tb - 2 + hh) : (tb + 126 + hh);
            float vk[5] = {0.f, 0.f, 0.f, 0.f, 0.f};
            if (tg >= 0 && tg < TT) {
                const int tok = x[b * TT + tg];
                const float4* src = (const float4*)(emb + (size_t)tok * EE + seg * 16);
                const float* aw = smATT + seg * 16;
                unsigned long long a2k[5] = {0ull, 0ull, 0ull, 0ull, 0ull};
                #pragma unroll
                for (int i = 0; i < 4; i++) {
                    float4 v = tf32x4(src[i]);
                    unsigned long long p01 = pack2(v.x, v.y);
                    unsigned long long p23 = pack2(v.z, v.w);
                    #pragma unroll
                    for (int k = 0; k < 5; k++) {
                        unsigned long long w01 = *(const unsigned long long*)(aw + k * EE + 4 * i);
                        unsigned long long w23 = *(const unsigned long long*)(aw + k * EE + 4 * i + 2);
                        a2k[k] = ffma2(p01, w01, a2k[k]);
                        a2k[k] = ffma2(p23, w23, a2k[k]);
                    }
                }
                #pragma unroll
                for (int k = 0; k < 5; k++) {
                    float2 f = unpack2(a2k[k]);
                    vk[k] = f.x + f.y;
                }
            }
            #pragma unroll
            for (int k = 0; k < 5; k++) {
                vk[k] += __shfl_xor_sync(0xffffffffu, vk[k], 1);
                vk[k] += __shfl_xor_sync(0xffffffffu, vk[k], 2);
                vk[k] += __shfl_xor_sync(0xffffffffu, vk[k], 4);
            }
            if (seg == 0) {
                const int ui = (hh < 2) ? hh : hh + 128;
                float* q = smQ + ui * 5;
                #pragma unroll
                for (int k = 0; k < 5; k++) q[k] = vk[k];
            }
        }
        __syncthreads();

        // ---- sigmoid scores: s[t] = sum_k q[t+k][k] ----
        if (tid < 128) {
            float s = smQ[tid * 5]
                    + smQ[(tid + 1) * 5 + 1]
                    + smQ[(tid + 2) * 5 + 2]
                    + smQ[(tid + 3) * 5 + 3]
                    + smQ[(tid + 4) * 5 + 4];
            smSIG[tid] = 1.f / (1.f + __expf(-(s + bias)));
        }

        // ---- tensor-core k-loop: warp computes 64t x 32o ----
        float acc[4][4][4];
        #pragma unroll
        for (int mb = 0; mb < 4; mb++)
            #pragma unroll
            for (int nb = 0; nb < 4; nb++)
                #pragma unroll
                for (int j = 0; j < 4; j++) acc[mb][nb][j] = 0.f;

        #pragma unroll
        for (int kb = 0; kb < 16; kb++) {
            const int kc = kb * 8;
            uint32_t b0[4], b1[4];
            #pragma unroll
            for (int nb = 0; nb < 4; nb++) {
                b0[nb] = wW[bBase + nb * 8 * RST + kc];
                b1[nb] = wW[bBase + nb * 8 * RST + kc + 4];
            }
            #pragma unroll
            for (int mb = 0; mb < 4; mb++) {
                const int ao = aBase + mb * 16 * RST + kc;
                const uint32_t a0 = wE[ao];
                const uint32_t a1 = wE[ao + 8 * RST];
                const uint32_t a2 = wE[ao + 4];
                const uint32_t a3 = wE[ao + 8 * RST + 4];
                #pragma unroll
                for (int nb = 0; nb < 4; nb++)
                    mma8(acc[mb][nb], a0, a1, a2, a3, b0[nb], b1[nb]);
            }
        }
        __syncthreads();   // smSIG ready for all warps; k-loop E reads done

        // ---- epilogue: apply sigma_t, max over t, reduce across lanes ----
        float vm[4][2];
        #pragma unroll
        for (int nb = 0; nb < 4; nb++) { vm[nb][0] = -INFINITY; vm[nb][1] = -INFINITY; }
        #pragma unroll
        for (int mb = 0; mb < 4; mb++) {
            const float s0 = smSIG[mh * 64 + mb * 16 + l4];
            const float s1 = smSIG[mh * 64 + mb * 16 + l4 + 8];
            #pragma unroll
            for (int nb = 0; nb < 4; nb++) {
                vm[nb][0] = fmaxf(vm[nb][0], fmaxf(s0 * acc[mb][nb][0], s1 * acc[mb][nb][2]));
                vm[nb][1] = fmaxf(vm[nb][1], fmaxf(s0 * acc[mb][nb][1], s1 * acc[mb][nb][3]));
            }
        }
        #pragma unroll
        for (int nb = 0; nb < 4; nb++) {
            #pragma unroll
            for (int j = 0; j < 2; j++) {
                float v = vm[nb][j];
                v = fmaxf(v, __shfl_xor_sync(0xffffffffu, v, 4));
                v = fmaxf(v, __shfl_xor_sync(0xffffffffu, v, 8));
                v = fmaxf(v, __shfl_xor_sync(0xffffffffu, v, 16));
                vm[nb][j] = v;
            }
        }
        if (l4 == 0) {   // lanes 0..3
            float* gp = g_part + (size_t)tile * 256 + mh * 128;
            #pragma unroll
            for (int nb = 0; nb < 4; nb++) {
                const int o = wo * 32 + nb * 8 + 2 * lane;
                gp[o]     = vm[nb][0];
                gp[o + 1] = vm[nb][1];
            }
        }
    }
}

__global__ void la_fin(const float* __restrict__ cnnb, float* __restrict__ out) {
    const int i = blockIdx.x * blockDim.x + threadIdx.x;   // b*128 + o
    const int b = i >> 7, o = i & 127;
    float m = -INFINITY;
    #pragma unroll
    for (int j = 0; j < 32; j++)
        m = fmaxf(m, g_part[((size_t)b * 32 + j) * 128 + o]);
    out[i] = tanhf(m + cnnb[o]);
}

extern "C" void kernel_launch(void* const* d_in, const int* in_sizes, int n_in,
                              void* d_out, int out_size) {
    const int*   x    = (const int*)d_in[0];
    const float* emb  = (const float*)d_in[1];
    const float* attw = (const float*)d_in[2];
    const float* attb = (const float*)d_in[3];
    const float* cnnw = (const float*)d_in[4];
    const float* cnnb = (const float*)d_in[5];
    float*       out  = (float*)d_out;

    cudaFuncSetAttribute(la_main, cudaFuncAttributeMaxDynamicSharedMemorySize, SMEM_DYN);
    la_main<<<GRID, 256, SMEM_DYN>>>(x, emb, attw, attb, cnnw);
    la_fin<<<(BB * OCC) / 256, 256>>>(cnnb, out);
}

// round 9
// speedup vs baseline: 3.1566x; 1.1837x over previous
#include <cuda_runtime.h>
#include <cuda_fp16.h>
#include <math.h>
#include <stdint.h>

#define BB 256
#define TT 2048
#define EE 128
#define OCC 128
#define NTILES 4096          // BB * TT / 128
#define GRID 148

// Stage buffers (fp32): stride 136 floats (544 B) -> conflict-free LDS.128 in convert
#define STF 136
// Half tiles (E, W): stride 136 halves (272 B) -> conflict-free fragment LDS.32
#define STH 136

// SMEM byte offsets
#define OFF_ST0  0
#define OFF_ST1  69632                     // 128*136*4
#define OFF_EH   139264                    // 128*136*2 = 34816
#define OFF_WH   174080
#define OFF_ATTW 208896                    // 5*128*4
#define OFF_Q    211456                    // 132*5*4
#define OFF_SIG  214096                    // 128*4
#define SMEM_DYN 214608

// per-(tile, t-half) partial maxes: 4096 * 2 * 128 floats = 4 MB static scratch
__device__ float g_part[NTILES * 2 * OCC];

static __device__ __forceinline__ unsigned long long ffma2(unsigned long long a,
                                                           unsigned long long b,
                                                           unsigned long long c) {
    unsigned long long d;
    asm("fma.rn.f32x2 %0, %1, %2, %3;" : "=l"(d) : "l"(a), "l"(b), "l"(c));
    return d;
}
static __device__ __forceinline__ float2 unpack2(unsigned long long v) {
    float2 r;
    asm("mov.b64 {%0, %1}, %2;" : "=f"(r.x), "=f"(r.y) : "l"(v));
    return r;
}
static __device__ __forceinline__ unsigned long long pack2(float lo, float hi) {
    unsigned long long v;
    asm("mov.b64 %0, {%1, %2};" : "=l"(v) : "f"(lo), "f"(hi));
    return v;
}
static __device__ __forceinline__ uint32_t smem_u32(const void* p) {
    uint32_t a;
    asm("{ .reg .u64 t; cvta.to.shared.u64 t, %1; cvt.u32.u64 %0, t; }" : "=r"(a) : "l"(p));
    return a;
}
static __device__ __forceinline__ void cpasync16(uint32_t dst, const void* src) {
    asm volatile("cp.async.cg.shared.global [%0], [%1], 16;" :: "r"(dst), "l"(src));
}
// m16n8k16 fp16 MMA, fp32 accum: D[t(m), o(n)], A row-major, B col-major
static __device__ __forceinline__ void mma16(float* c,
                                             uint32_t a0, uint32_t a1, uint32_t a2, uint32_t a3,
                                             uint32_t b0, uint32_t b1) {
    asm volatile(
        "mma.sync.aligned.m16n8k16.row.col.f32.f16.f16.f32 "
        "{%0,%1,%2,%3}, {%4,%5,%6,%7}, {%8,%9}, {%0,%1,%2,%3};"
        : "+f"(c[0]), "+f"(c[1]), "+f"(c[2]), "+f"(c[3])
        : "r"(a0), "r"(a1), "r"(a2), "r"(a3), "r"(b0), "r"(b1));
}

__global__ void __launch_bounds__(256, 1) la_main(
    const int* __restrict__ x, const float* __restrict__ emb,
    const float* __restrict__ attw, const float* __restrict__ attb,
    const float* __restrict__ cnnw)
{
    extern __shared__ char sm[];
    float* smATT = (float*)(sm + OFF_ATTW);
    float* smQ   = (float*)(sm + OFF_Q);
    float* smSIG = (float*)(sm + OFF_SIG);
    const uint32_t smb = smem_u32(sm);

    const int tid  = threadIdx.x;
    const int lane = tid & 31;
    const int w    = tid >> 5;
    const int wo   = w & 3;          // o-quadrant (32 o's)
    const int mh   = w >> 2;         // t-half (64 t's)
    const int l4   = lane >> 2;
    const int lm   = lane & 3;
    const int r    = tid >> 1;       // row owned (2 threads/row)
    const int h    = tid & 1;        // 64-element half of the row

    // ---- one-time: W -> fp16 tile, att_w -> smem ----
    {
        const float4* src = (const float4*)(cnnw + r * EE + h * 64);
        uint2* dst = (uint2*)(sm + OFF_WH + (r * STH + h * 64) * 2);
        #pragma unroll
        for (int i = 0; i < 16; i++) {
            float4 v = src[i];
            __half2 p01 = __floats2half2_rn(v.x, v.y);
            __half2 p23 = __floats2half2_rn(v.z, v.w);
            uint2 u; u.x = *(uint32_t*)&p01; u.y = *(uint32_t*)&p23;
            dst[i] = u;
        }
    }
    for (int i = tid; i < 5 * EE; i += 256) smATT[i] = attw[i];
    const float bias = attb[0];
    __syncthreads();

    const uint32_t* hE = (const uint32_t*)(sm + OFF_EH);  // index unit = 2 halves
    const uint32_t* hW = (const uint32_t*)(sm + OFF_WH);
    const int aBase = (mh * 64 + l4) * (STH / 2) + lm;
    const int bBase = (wo * 32 + l4) * (STH / 2) + lm;
    const uint32_t stDst = smb + (uint32_t)((r * STF + h * 68) * 4);

    // ---- prologue prefetch: tile = blockIdx.x -> stage0 ----
    {
        const int tile = blockIdx.x;
        const int tok = x[(tile >> 4) * TT + ((tile & 15) << 7) + r];
        const float4* src = (const float4*)(emb + (size_t)tok * EE + h * 64);
        #pragma unroll
        for (int i = 0; i < 16; i++) cpasync16(stDst + OFF_ST0 + 16 * i, src + i);
    }
    asm volatile("cp.async.commit_group;" ::: "memory");

    int buf = 0;
    for (int tile = blockIdx.x; tile < NTILES; tile += GRID) {
        const int b  = tile >> 4;
        const int tb = (tile & 15) << 7;
        const bool has_next = (tile + GRID) < NTILES;

        // ---- prefetch next tile into the other stage buffer ----
        if (has_next) {
            const int nt = tile + GRID;
            const int tok = x[(nt >> 4) * TT + ((nt & 15) << 7) + r];
            const float4* src = (const float4*)(emb + (size_t)tok * EE + h * 64);
            const uint32_t d = stDst + (buf ? OFF_ST0 : OFF_ST1);
            #pragma unroll
            for (int i = 0; i < 16; i++) cpasync16(d + 16 * i, src + i);
            asm volatile("cp.async.commit_group;" ::: "memory");
            asm volatile("cp.async.wait_group 1;" ::: "memory");
        } else {
            asm volatile("cp.async.wait_group 0;" ::: "memory");
        }
        __syncthreads();   // stage[buf] visible to all

        // ---- convert stage -> fp16 E tile + in-register window-dot partials ----
        {
            const float* srow = (const float*)(sm + (buf ? OFF_ST1 : OFF_ST0))
                                + r * STF + h * 68;
            uint2* drow = (uint2*)(sm + OFF_EH + (r * STH + h * 64) * 2);
            const float* aw = smATT + h * 64;
            unsigned long long a2k[5] = {0ull, 0ull, 0ull, 0ull, 0ull};
            #pragma unroll
            for (int i = 0; i < 16; i++) {
                float4 v = *(const float4*)(srow + 4 * i);
                __half2 p01 = __floats2half2_rn(v.x, v.y);
                __half2 p23 = __floats2half2_rn(v.z, v.w);
                uint2 u; u.x = *(uint32_t*)&p01; u.y = *(uint32_t*)&p23;
                drow[i] = u;
                unsigned long long q01 = pack2(v.x, v.y);
                unsigned long long q23 = pack2(v.z, v.w);
                #pragma unroll
                for (int k = 0; k < 5; k++) {
                    unsigned long long w01 = *(const unsigned long long*)(aw + k * EE + 4 * i);
                    unsigned long long w23 = *(const unsigned long long*)(aw + k * EE + 4 * i + 2);
                    a2k[k] = ffma2(q01, w01, a2k[k]);
                    a2k[k] = ffma2(q23, w23, a2k[k]);
                }
            }
            float qv[5];
            #pragma unroll
            for (int k = 0; k < 5; k++) {
                float2 f = unpack2(a2k[k]);
                float s = f.x + f.y;
                s += __shfl_xor_sync(0xffffffffu, s, 1);   // combine two row-halves
                qv[k] = s;
            }
            if (h == 0) {
                float* q = smQ + (r + 2) * 5;
                #pragma unroll
                for (int k = 0; k < 5; k++) q[k] = qv[k];
            }
        }
        // halo rows (t-2, t-1, t+128, t+129) — warp 0, 8 threads/row, fp32 exact
        if (tid < 32) {
            const int hh = tid >> 3, seg = tid & 7;
            const int tg = (hh < 2) ? (tb - 2 + hh) : (tb + 126 + hh);
            float vk[5] = {0.f, 0.f, 0.f, 0.f, 0.f};
            if (tg >= 0 && tg < TT) {
                const int tok = x[b * TT + tg];
                const float4* src = (const float4*)(emb + (size_t)tok * EE + seg * 16);
                const float* aw = smATT + seg * 16;
                unsigned long long a2k[5] = {0ull, 0ull, 0ull, 0ull, 0ull};
                #pragma unroll
                for (int i = 0; i < 4; i++) {
                    float4 v = src[i];
                    unsigned long long q01 = pack2(v.x, v.y);
                    unsigned long long q23 = pack2(v.z, v.w);
                    #pragma unroll
                    for (int k = 0; k < 5; k++) {
                        unsigned long long w01 = *(const unsigned long long*)(aw + k * EE + 4 * i);
                        unsigned long long w23 = *(const unsigned long long*)(aw + k * EE + 4 * i + 2);
                        a2k[k] = ffma2(q01, w01, a2k[k]);
                        a2k[k] = ffma2(q23, w23, a2k[k]);
                    }
                }
                #pragma unroll
                for (int k = 0; k < 5; k++) {
                    float2 f = unpack2(a2k[k]);
                    vk[k] = f.x + f.y;
                }
            }
            #pragma unroll
            for (int k = 0; k < 5; k++) {
                vk[k] += __shfl_xor_sync(0xffffffffu, vk[k], 1);
                vk[k] += __shfl_xor_sync(0xffffffffu, vk[k], 2);
                vk[k] += __shfl_xor_sync(0xffffffffu, vk[k], 4);
            }
            if (seg == 0) {
                const int ui = (hh < 2) ? hh : hh + 128;
                float* q = smQ + ui * 5;
                #pragma unroll
                for (int k = 0; k < 5; k++) q[k] = vk[k];
            }
        }
        __syncthreads();

        // ---- sigmoid scores ----
        if (tid < 128) {
            float s = smQ[tid * 5]
                    + smQ[(tid + 1) * 5 + 1]
                    + smQ[(tid + 2) * 5 + 2]
                    + smQ[(tid + 3) * 5 + 3]
                    + smQ[(tid + 4) * 5 + 4];
            smSIG[tid] = 1.f / (1.f + __expf(-(s + bias)));
        }
        __syncthreads();   // E-half + sig ready

        // ---- fp16 tensor-core k-loop: warp computes 64t x 32o ----
        float acc[4][4][4];
        #pragma unroll
        for (int mb = 0; mb < 4; mb++)
            #pragma unroll
            for (int nb = 0; nb < 4; nb++)
                #pragma unroll
                for (int j = 0; j < 4; j++) acc[mb][nb][j] = 0.f;

        #pragma unroll
        for (int kb = 0; kb < 8; kb++) {
            const int kc = kb * 8;   // in uint32 units (16 halves per kb)
            uint32_t b0[4], b1[4];
            #pragma unroll
            for (int nb = 0; nb < 4; nb++) {
                b0[nb] = hW[bBase + nb * 8 * (STH / 2) + kc];
                b1[nb] = hW[bBase + nb * 8 * (STH / 2) + kc + 4];
            }
            #pragma unroll
            for (int mb = 0; mb < 4; mb++) {
                const int ao = aBase + mb * 16 * (STH / 2) + kc;
                const uint32_t a0 = hE[ao];
                const uint32_t a1 = hE[ao + 8 * (STH / 2)];
                const uint32_t a2 = hE[ao + 4];
                const uint32_t a3 = hE[ao + 8 * (STH / 2) + 4];
                #pragma unroll
                for (int nb = 0; nb < 4; nb++)
                    mma16(acc[mb][nb], a0, a1, a2, a3, b0[nb], b1[nb]);
            }
        }
        __syncthreads();   // E/sig reads done before next convert overwrites

        // ---- epilogue: apply sigma_t, max over t, lane-reduce, store partials ----
        float vm[4][2];
        #pragma unroll
        for (int nb = 0; nb < 4; nb++) { vm[nb][0] = -INFINITY; vm[nb][1] = -INFINITY; }
        #pragma unroll
        for (int mb = 0; mb < 4; mb++) {
            const float s0 = smSIG[mh * 64 + mb * 16 + l4];
            const float s1 = smSIG[mh * 64 + mb * 16 + l4 + 8];
            #pragma unroll
            for (int nb = 0; nb < 4; nb++) {
                vm[nb][0] = fmaxf(vm[nb][0], fmaxf(s0 * acc[mb][nb][0], s1 * acc[mb][nb][2]));
                vm[nb][1] = fmaxf(vm[nb][1], fmaxf(s0 * acc[mb][nb][1], s1 * acc[mb][nb][3]));
            }
        }
        #pragma unroll
        for (int nb = 0; nb < 4; nb++) {
            #pragma unroll
            for (int j = 0; j < 2; j++) {
                float v = vm[nb][j];
                v = fmaxf(v, __shfl_xor_sync(0xffffffffu, v, 4));
                v = fmaxf(v, __shfl_xor_sync(0xffffffffu, v, 8));
                v = fmaxf(v, __shfl_xor_sync(0xffffffffu, v, 16));
                vm[nb][j] = v;
            }
        }
        if (l4 == 0) {   // lanes 0..3
            float* gp = g_part + (size_t)tile * 256 + mh * 128;
            #pragma unroll
            for (int nb = 0; nb < 4; nb++) {
                const int o = wo * 32 + nb * 8 + 2 * lane;
                gp[o]     = vm[nb][0];
                gp[o + 1] = vm[nb][1];
            }
        }
        buf ^= 1;
    }
}

__global__ void la_fin(const float* __restrict__ cnnb, float* __restrict__ out) {
    const int i = blockIdx.x * blockDim.x + threadIdx.x;   // b*128 + o
    const int b = i >> 7, o = i & 127;
    float m = -INFINITY;
    #pragma unroll
    for (int j = 0; j < 32; j++)
        m = fmaxf(m, g_part[((size_t)b * 32 + j) * 128 + o]);
    out[i] = tanhf(m + cnnb[o]);
}

extern "C" void kernel_launch(void* const* d_in, const int* in_sizes, int n_in,
                              void* d_out, int out_size) {
    const int*   x    = (const int*)d_in[0];
    const float* emb  = (const float*)d_in[1];
    const float* attw = (const float*)d_in[2];
    const float* attb = (const float*)d_in[3];
    const float* cnnw = (const float*)d_in[4];
    const float* cnnb = (const float*)d_in[5];
    float*       out  = (float*)d_out;

    cudaFuncSetAttribute(la_main, cudaFuncAttributeMaxDynamicSharedMemorySize, SMEM_DYN);
    la_main<<<GRID, 256, SMEM_DYN>>>(x, emb, attw, attb, cnnw);
    la_fin<<<(BB * OCC) / 256, 256>>>(cnnb, out);
}

// round 10
// speedup vs baseline: 5.4711x; 1.7332x over previous
#include <cuda_runtime.h>
#include <cuda_fp16.h>
#include <math.h>
#include <stdint.h>

#define BB 256
#define TT 2048
#define EE 128
#define OCC 128
#define VOC1 50001
#define NTILES 4096          // BB * TT / 128
#define GRID 148
#define STH 136              // half-stride of E/W tiles (68 uint32) -> conflict-free frags
#define STU (STH / 2)        // 68

// SMEM byte offsets
#define OFF_E0   0                         // E tile buf0: 128 x 136 halves = 34816
#define OFF_E1   34816
#define OFF_W    69632                     // W tile: 136 x 136 halves = 36992
#define OFF_Q    106624                    // q: 132 rows x 8 floats = 4224
#define OFF_SIG  110848                    // 128 floats
#define OFF_ATT  111360                    // 5 x 128 floats (halo path)
#define SMEM_DYN 113920

__device__ float g_part[NTILES * 2 * OCC];                 // 4 MB partial maxes
__device__ __align__(16) __half g_emb16[VOC1 * EE];        // 12.8 MB fp16 table

static __device__ __forceinline__ uint32_t smem_u32(const void* p) {
    uint32_t a;
    asm("{ .reg .u64 t; cvta.to.shared.u64 t, %1; cvt.u32.u64 %0, t; }" : "=r"(a) : "l"(p));
    return a;
}
static __device__ __forceinline__ void cpasync16(uint32_t dst, const void* src) {
    asm volatile("cp.async.cg.shared.global [%0], [%1], 16;" :: "r"(dst), "l"(src));
}
static __device__ __forceinline__ void mma16(float* c,
                                             uint32_t a0, uint32_t a1, uint32_t a2, uint32_t a3,
                                             uint32_t b0, uint32_t b1) {
    asm volatile(
        "mma.sync.aligned.m16n8k16.row.col.f32.f16.f16.f32 "
        "{%0,%1,%2,%3}, {%4,%5,%6,%7}, {%8,%9}, {%0,%1,%2,%3};"
        : "+f"(c[0]), "+f"(c[1]), "+f"(c[2]), "+f"(c[3])
        : "r"(a0), "r"(a1), "r"(a2), "r"(a3), "r"(b0), "r"(b1));
}

// ---- one-shot fp32 -> fp16 table conversion (runs every replay; deterministic) ----
__global__ void emb_conv(const float* __restrict__ emb) {
    const int i = blockIdx.x * blockDim.x + threadIdx.x;   // 8 halves per thread
    if (i >= (VOC1 * EE) / 8) return;
    const float4* s = (const float4*)emb + 2 * i;
    float4 v0 = s[0], v1 = s[1];
    __half2 h0 = __floats2half2_rn(v0.x, v0.y);
    __half2 h1 = __floats2half2_rn(v0.z, v0.w);
    __half2 h2 = __floats2half2_rn(v1.x, v1.y);
    __half2 h3 = __floats2half2_rn(v1.z, v1.w);
    uint4 u;
    u.x = *(uint32_t*)&h0; u.y = *(uint32_t*)&h1;
    u.z = *(uint32_t*)&h2; u.w = *(uint32_t*)&h3;
    ((uint4*)g_emb16)[i] = u;
}

__global__ void __launch_bounds__(256, 1) la_main(
    const int* __restrict__ x, const float* __restrict__ attw,
    const float* __restrict__ attb, const float* __restrict__ cnnw)
{
    extern __shared__ char sm[];
    float* smQ   = (float*)(sm + OFF_Q);     // [u][8], u = 0..131
    float* smSIG = (float*)(sm + OFF_SIG);
    float* smATT = (float*)(sm + OFF_ATT);
    const uint32_t smb = smem_u32(sm);

    const int tid  = threadIdx.x;
    const int lane = tid & 31;
    const int w    = tid >> 5;
    const int wo   = w & 3;          // o-quadrant
    const int mh   = w >> 2;         // t-half
    const int l4   = lane >> 2;
    const int lm   = lane & 3;
    const int r    = tid >> 1;       // row owned in gather (2 threads/row)
    const int h    = tid & 1;        // 64-half segment

    // ---- one-time: W fp16 tile (rows 0..127 = cnn_w, 128..132 = att_w, 133..135 = 0) ----
    {
        const float4* src = (const float4*)(cnnw + r * EE + h * 64);
        uint2* dst = (uint2*)(sm + OFF_W + (r * STH + h * 64) * 2);
        #pragma unroll
        for (int i = 0; i < 16; i++) {
            float4 v = src[i];
            __half2 p01 = __floats2half2_rn(v.x, v.y);
            __half2 p23 = __floats2half2_rn(v.z, v.w);
            uint2 u; u.x = *(uint32_t*)&p01; u.y = *(uint32_t*)&p23;
            dst[i] = u;
        }
    }
    if (tid < 64) {  // 8 extra rows, 8 threads/row, 16 halves each
        const int j = tid >> 3, seg = tid & 7;
        uint2* dst = (uint2*)(sm + OFF_W + ((128 + j) * STH + seg * 16) * 2);
        #pragma unroll
        for (int i = 0; i < 4; i++) {
            float4 v = (j < 5) ? *(const float4*)(attw + j * EE + seg * 16 + 4 * i)
                               : make_float4(0.f, 0.f, 0.f, 0.f);
            __half2 p01 = __floats2half2_rn(v.x, v.y);
            __half2 p23 = __floats2half2_rn(v.z, v.w);
            uint2 u; u.x = *(uint32_t*)&p01; u.y = *(uint32_t*)&p23;
            dst[i] = u;
        }
    }
    for (int i = tid; i < 5 * EE; i += 256) smATT[i] = attw[i];
    const float bias = attb[0];
    __syncthreads();

    const uint32_t* hW = (const uint32_t*)(sm + OFF_W);
    const int aBase = (mh * 64 + l4) * STU + lm;
    const int bBase = (wo * 32 + l4) * STU + lm;
    const int bqBase = (128 + l4) * STU + lm;          // q columns (n = 128..135)
    const uint32_t eDst = (uint32_t)((r * STH + h * 64) * 2);

    // ---- prologue prefetch: first tile -> E0 ----
    {
        const int tile = blockIdx.x;
        const int tok = x[(tile >> 4) * TT + ((tile & 15) << 7) + r];
        const __half* src = g_emb16 + (size_t)tok * EE + h * 64;
        #pragma unroll
        for (int i = 0; i < 8; i++) cpasync16(smb + OFF_E0 + eDst + 16 * i, src + 8 * i);
    }
    asm volatile("cp.async.commit_group;" ::: "memory");

    int buf = 0;
    for (int tile = blockIdx.x; tile < NTILES; tile += GRID) {
        const int b  = tile >> 4;
        const int tb = (tile & 15) << 7;
        const bool has_next = (tile + GRID) < NTILES;

        if (has_next) {
            const int nt = tile + GRID;
            const int tok = x[(nt >> 4) * TT + ((nt & 15) << 7) + r];
            const __half* src = g_emb16 + (size_t)tok * EE + h * 64;
            const uint32_t d = smb + (buf ? OFF_E0 : OFF_E1) + eDst;
            #pragma unroll
            for (int i = 0; i < 8; i++) cpasync16(d + 16 * i, src + 8 * i);
            asm volatile("cp.async.commit_group;" ::: "memory");
            asm volatile("cp.async.wait_group 1;" ::: "memory");
        } else {
            asm volatile("cp.async.wait_group 0;" ::: "memory");
        }
        __syncthreads();   // E[buf] visible

        // ---- halo q (warp 1): rows t-2, t-1, t+128, t+129 -> smQ u = 0,1,130,131 ----
        if (w == 1) {
            const int hh = lane >> 3, seg = lane & 7;
            const int tg = (hh < 2) ? (tb - 2 + hh) : (tb + 126 + hh);
            float vk[5] = {0.f, 0.f, 0.f, 0.f, 0.f};
            if (tg >= 0 && tg < TT) {
                const int tok = x[b * TT + tg];
                const uint4* src = (const uint4*)(g_emb16 + (size_t)tok * EE + seg * 16);
                const float* aw = smATT + seg * 16;
                #pragma unroll
                for (int c8 = 0; c8 < 2; c8++) {
                    uint4 u = src[c8];
                    float f[8];
                    f[0] = __low2float(*(__half2*)&u.x);  f[1] = __high2float(*(__half2*)&u.x);
                    f[2] = __low2float(*(__half2*)&u.y);  f[3] = __high2float(*(__half2*)&u.y);
                    f[4] = __low2float(*(__half2*)&u.z);  f[5] = __high2float(*(__half2*)&u.z);
                    f[6] = __low2float(*(__half2*)&u.w);  f[7] = __high2float(*(__half2*)&u.w);
                    #pragma unroll
                    for (int e = 0; e < 8; e++)
                        #pragma unroll
                        for (int k = 0; k < 5; k++)
                            vk[k] += f[e] * aw[k * EE + c8 * 8 + e];
                }
            }
            #pragma unroll
            for (int k = 0; k < 5; k++) {
                vk[k] += __shfl_xor_sync(0xffffffffu, vk[k], 1);
                vk[k] += __shfl_xor_sync(0xffffffffu, vk[k], 2);
                vk[k] += __shfl_xor_sync(0xffffffffu, vk[k], 4);
            }
            if (seg == 0) {
                const int u = (hh < 2) ? hh : hh + 128;
                #pragma unroll
                for (int k = 0; k < 5; k++) smQ[u * 8 + k] = vk[k];
            }
        }

        // ---- fp16 k-loop: 64t x 32o per warp (+ q columns on wo==3) ----
        const uint32_t* hE = (const uint32_t*)(sm + (buf ? OFF_E1 : OFF_E0));
        float acc[4][4][4];
        float accq[4][4];
        #pragma unroll
        for (int mb = 0; mb < 4; mb++) {
            #pragma unroll
            for (int nb = 0; nb < 4; nb++)
                #pragma unroll
                for (int j = 0; j < 4; j++) acc[mb][nb][j] = 0.f;
            #pragma unroll
            for (int j = 0; j < 4; j++) accq[mb][j] = 0.f;
        }

        #pragma unroll
        for (int kb = 0; kb < 8; kb++) {
            const int kc = kb * 8;
            uint32_t b0[4], b1[4], bq0 = 0, bq1 = 0;
            #pragma unroll
            for (int nb = 0; nb < 4; nb++) {
                b0[nb] = hW[bBase + nb * 8 * STU + kc];
                b1[nb] = hW[bBase + nb * 8 * STU + kc + 4];
            }
            if (wo == 3) {
                bq0 = hW[bqBase + kc];
                bq1 = hW[bqBase + kc + 4];
            }
            #pragma unroll
            for (int mb = 0; mb < 4; mb++) {
                const int ao = aBase + mb * 16 * STU + kc;
                const uint32_t a0 = hE[ao];
                const uint32_t a1 = hE[ao + 8 * STU];
                const uint32_t a2 = hE[ao + 4];
                const uint32_t a3 = hE[ao + 8 * STU + 4];
                #pragma unroll
                for (int nb = 0; nb < 4; nb++)
                    mma16(acc[mb][nb], a0, a1, a2, a3, b0[nb], b1[nb]);
                if (wo == 3)
                    mma16(accq[mb], a0, a1, a2, a3, bq0, bq1);
            }
        }

        // ---- wo==3: scatter q fragments (cols j = 2lm, 2lm+1; keep j < 5) ----
        if (wo == 3 && lm < 3) {
            #pragma unroll
            for (int mb = 0; mb < 4; mb++) {
                const int u0 = mh * 64 + mb * 16 + l4 + 2;
                const int j0 = 2 * lm;
                smQ[u0 * 8 + j0] = accq[mb][0];
                smQ[(u0 + 8) * 8 + j0] = accq[mb][2];
                if (j0 + 1 < 5) {
                    smQ[u0 * 8 + j0 + 1] = accq[mb][1];
                    smQ[(u0 + 8) * 8 + j0 + 1] = accq[mb][3];
                }
            }
        }
        __syncthreads();   // q complete; E[buf] reads done

        // ---- sigmoid: s[t] = sum_k q[t+k][k] ----
        if (tid < 128) {
            float s = smQ[tid * 8]
                    + smQ[(tid + 1) * 8 + 1]
                    + smQ[(tid + 2) * 8 + 2]
                    + smQ[(tid + 3) * 8 + 3]
                    + smQ[(tid + 4) * 8 + 4];
            smSIG[tid] = 1.f / (1.f + __expf(-(s + bias)));
        }
        __syncthreads();

        // ---- epilogue: sigma_t * D, max over t, lane-reduce, store partials ----
        float vm[4][2];
        #pragma unroll
        for (int nb = 0; nb < 4; nb++) { vm[nb][0] = -INFINITY; vm[nb][1] = -INFINITY; }
        #pragma unroll
        for (int mb = 0; mb < 4; mb++) {
            const float s0 = smSIG[mh * 64 + mb * 16 + l4];
            const float s1 = smSIG[mh * 64 + mb * 16 + l4 + 8];
            #pragma unroll
            for (int nb = 0; nb < 4; nb++) {
                vm[nb][0] = fmaxf(vm[nb][0], fmaxf(s0 * acc[mb][nb][0], s1 * acc[mb][nb][2]));
                vm[nb][1] = fmaxf(vm[nb][1], fmaxf(s0 * acc[mb][nb][1], s1 * acc[mb][nb][3]));
            }
        }
        #pragma unroll
        for (int nb = 0; nb < 4; nb++) {
            #pragma unroll
            for (int j = 0; j < 2; j++) {
                float v = vm[nb][j];
                v = fmaxf(v, __shfl_xor_sync(0xffffffffu, v, 4));
                v = fmaxf(v, __shfl_xor_sync(0xffffffffu, v, 8));
                v = fmaxf(v, __shfl_xor_sync(0xffffffffu, v, 16));
                vm[nb][j] = v;
            }
        }
        if (l4 == 0) {   // lanes 0..3
            float* gp = g_part + (size_t)tile * 256 + mh * 128;
            #pragma unroll
            for (int nb = 0; nb < 4; nb++) {
                const int o = wo * 32 + nb * 8 + 2 * lane;
                gp[o]     = vm[nb][0];
                gp[o + 1] = vm[nb][1];
            }
        }
        buf ^= 1;
    }
}

__global__ void la_fin(const float* __restrict__ cnnb, float* __restrict__ out) {
    const int i = blockIdx.x * blockDim.x + threadIdx.x;   // b*128 + o
    const int b = i >> 7, o = i & 127;
    float m = -INFINITY;
    #pragma unroll
    for (int j = 0; j < 32; j++)
        m = fmaxf(m, g_part[((size_t)b * 32 + j) * 128 + o]);
    out[i] = tanhf(m + cnnb[o]);
}

extern "C" void kernel_launch(void* const* d_in, const int* in_sizes, int n_in,
                              void* d_out, int out_size) {
    const int*   x    = (const int*)d_in[0];
    const float* emb  = (const float*)d_in[1];
    const float* attw = (const float*)d_in[2];
    const float* attb = (const float*)d_in[3];
    const float* cnnw = (const float*)d_in[4];
    const float* cnnb = (const float*)d_in[5];
    float*       out  = (float*)d_out;

    emb_conv<<<(VOC1 * EE / 8 + 255) / 256, 256>>>(emb);
    cudaFuncSetAttribute(la_main, cudaFuncAttributeMaxDynamicSharedMemorySize, SMEM_DYN);
    la_main<<<GRID, 256, SMEM_DYN>>>(x, attw, attb, cnnw);
    la_fin<<<(BB * OCC) / 256, 256>>>(cnnb, out);
}

// round 11
// speedup vs baseline: 5.4856x; 1.0026x over previous
#include <cuda_runtime.h>
#include <cuda_fp16.h>
#include <math.h>
#include <stdint.h>

#define BB 256
#define TT 2048
#define EE 128
#define OCC 128
#define VOC1 50001
#define NTILES 4096          // BB * TT / 128
#define GRID 148
#define STH 136              // half-stride of E/W tiles (68 uint32) -> conflict-free frags
#define STU (STH / 2)        // 68

// SMEM byte offsets
#define OFF_E0   0                         // E tile buf0: 128 x 136 halves = 34816
#define OFF_E1   34816
#define OFF_W    69632                     // W tile: 136 x 136 halves = 36992
#define OFF_Q    106624                    // q: 132 rows x 8 floats = 4224
#define OFF_SIG  110848                    // 128 floats
#define OFF_ATT  111360                    // 5 x 128 floats (halo path)
#define SMEM_DYN 113920

__device__ float g_part[NTILES * 2 * OCC];                 // 4 MB partial maxes
__device__ __align__(16) __half g_emb16[VOC1 * EE];        // 12.8 MB fp16 table

static __device__ __forceinline__ uint32_t smem_u32(const void* p) {
    uint32_t a;
    asm("{ .reg .u64 t; cvta.to.shared.u64 t, %1; cvt.u32.u64 %0, t; }" : "=r"(a) : "l"(p));
    return a;
}
static __device__ __forceinline__ void cpasync16(uint32_t dst, const void* src) {
    asm volatile("cp.async.cg.shared.global [%0], [%1], 16;" :: "r"(dst), "l"(src));
}
static __device__ __forceinline__ void mma16(float* c,
                                             uint32_t a0, uint32_t a1, uint32_t a2, uint32_t a3,
                                             uint32_t b0, uint32_t b1) {
    asm volatile(
        "mma.sync.aligned.m16n8k16.row.col.f32.f16.f16.f32 "
        "{%0,%1,%2,%3}, {%4,%5,%6,%7}, {%8,%9}, {%0,%1,%2,%3};"
        : "+f"(c[0]), "+f"(c[1]), "+f"(c[2]), "+f"(c[3])
        : "r"(a0), "r"(a1), "r"(a2), "r"(a3), "r"(b0), "r"(b1));
}

// ---- one-shot fp32 -> fp16 table conversion (runs every replay; deterministic) ----
__global__ void emb_conv(const float* __restrict__ emb) {
    const int i = blockIdx.x * blockDim.x + threadIdx.x;   // 8 halves per thread
    if (i >= (VOC1 * EE) / 8) return;
    const float4* s = (const float4*)emb + 2 * i;
    float4 v0 = s[0], v1 = s[1];
    __half2 h0 = __floats2half2_rn(v0.x, v0.y);
    __half2 h1 = __floats2half2_rn(v0.z, v0.w);
    __half2 h2 = __floats2half2_rn(v1.x, v1.y);
    __half2 h3 = __floats2half2_rn(v1.z, v1.w);
    uint4 u;
    u.x = *(uint32_t*)&h0; u.y = *(uint32_t*)&h1;
    u.z = *(uint32_t*)&h2; u.w = *(uint32_t*)&h3;
    ((uint4*)g_emb16)[i] = u;
}

__global__ void __launch_bounds__(256, 1) la_main(
    const int* __restrict__ x, const float* __restrict__ attw,
    const float* __restrict__ attb, const float* __restrict__ cnnw)
{
    extern __shared__ char sm[];
    float* smQ   = (float*)(sm + OFF_Q);     // [u][8], u = 0..131
    float* smSIG = (float*)(sm + OFF_SIG);
    float* smATT = (float*)(sm + OFF_ATT);
    const uint32_t smb = smem_u32(sm);

    const int tid  = threadIdx.x;
    const int lane = tid & 31;
    const int w    = tid >> 5;
    const int wo   = w & 3;          // o-quadrant
    const int mh   = w >> 2;         // t-half
    const int l4   = lane >> 2;
    const int lm   = lane & 3;
    const int r    = tid >> 1;       // row owned in gather (2 threads/row)
    const int h    = tid & 1;        // 64-half segment

    // ---- one-time: W fp16 tile (rows 0..127 = cnn_w, 128..132 = att_w, 133..135 = 0) ----
    {
        const float4* src = (const float4*)(cnnw + r * EE + h * 64);
        uint2* dst = (uint2*)(sm + OFF_W + (r * STH + h * 64) * 2);
        #pragma unroll
        for (int i = 0; i < 16; i++) {
            float4 v = src[i];
            __half2 p01 = __floats2half2_rn(v.x, v.y);
            __half2 p23 = __floats2half2_rn(v.z, v.w);
            uint2 u; u.x = *(uint32_t*)&p01; u.y = *(uint32_t*)&p23;
            dst[i] = u;
        }
    }
    if (tid < 64) {  // 8 extra rows, 8 threads/row, 16 halves each
        const int j = tid >> 3, seg = tid & 7;
        uint2* dst = (uint2*)(sm + OFF_W + ((128 + j) * STH + seg * 16) * 2);
        #pragma unroll
        for (int i = 0; i < 4; i++) {
            float4 v = (j < 5) ? *(const float4*)(attw + j * EE + seg * 16 + 4 * i)
                               : make_float4(0.f, 0.f, 0.f, 0.f);
            __half2 p01 = __floats2half2_rn(v.x, v.y);
            __half2 p23 = __floats2half2_rn(v.z, v.w);
            uint2 u; u.x = *(uint32_t*)&p01; u.y = *(uint32_t*)&p23;
            dst[i] = u;
        }
    }
    for (int i = tid; i < 5 * EE; i += 256) smATT[i] = attw[i];
    const float bias = attb[0];
    __syncthreads();

    const uint32_t* hW = (const uint32_t*)(sm + OFF_W);
    const int aBase = (mh * 64 + l4) * STU + lm;
    const int bBase = (wo * 32 + l4) * STU + lm;
    const int bqBase = (128 + l4) * STU + lm;          // q columns (n = 128..135)
    const uint32_t eDst = (uint32_t)((r * STH + h * 64) * 2);

    // ---- prologue prefetch: first tile -> E0 ----
    {
        const int tile = blockIdx.x;
        const int tok = x[(tile >> 4) * TT + ((tile & 15) << 7) + r];
        const __half* src = g_emb16 + (size_t)tok * EE + h * 64;
        #pragma unroll
        for (int i = 0; i < 8; i++) cpasync16(smb + OFF_E0 + eDst + 16 * i, src + 8 * i);
    }
    asm volatile("cp.async.commit_group;" ::: "memory");

    int buf = 0;
    for (int tile = blockIdx.x; tile < NTILES; tile += GRID) {
        const int b  = tile >> 4;
        const int tb = (tile & 15) << 7;
        const bool has_next = (tile + GRID) < NTILES;

        if (has_next) {
            const int nt = tile + GRID;
            const int tok = x[(nt >> 4) * TT + ((nt & 15) << 7) + r];
            const __half* src = g_emb16 + (size_t)tok * EE + h * 64;
            const uint32_t d = smb + (buf ? OFF_E0 : OFF_E1) + eDst;
            #pragma unroll
            for (int i = 0; i < 8; i++) cpasync16(d + 16 * i, src + 8 * i);
            asm volatile("cp.async.commit_group;" ::: "memory");
            asm volatile("cp.async.wait_group 1;" ::: "memory");
        } else {
            asm volatile("cp.async.wait_group 0;" ::: "memory");
        }
        __syncthreads();   // E[buf] visible

        // ---- halo q (warp 1): rows t-2, t-1, t+128, t+129 -> smQ u = 0,1,130,131 ----
        if (w == 1) {
            const int hh = lane >> 3, seg = lane & 7;
            const int tg = (hh < 2) ? (tb - 2 + hh) : (tb + 126 + hh);
            float vk[5] = {0.f, 0.f, 0.f, 0.f, 0.f};
            if (tg >= 0 && tg < TT) {
                const int tok = x[b * TT + tg];
                const uint4* src = (const uint4*)(g_emb16 + (size_t)tok * EE + seg * 16);
                const float* aw = smATT + seg * 16;
                #pragma unroll
                for (int c8 = 0; c8 < 2; c8++) {
                    uint4 u = src[c8];
                    float f[8];
                    f[0] = __low2float(*(__half2*)&u.x);  f[1] = __high2float(*(__half2*)&u.x);
                    f[2] = __low2float(*(__half2*)&u.y);  f[3] = __high2float(*(__half2*)&u.y);
                    f[4] = __low2float(*(__half2*)&u.z);  f[5] = __high2float(*(__half2*)&u.z);
                    f[6] = __low2float(*(__half2*)&u.w);  f[7] = __high2float(*(__half2*)&u.w);
                    #pragma unroll
                    for (int e = 0; e < 8; e++)
                        #pragma unroll
                        for (int k = 0; k < 5; k++)
                            vk[k] += f[e] * aw[k * EE + c8 * 8 + e];
                }
            }
            #pragma unroll
            for (int k = 0; k < 5; k++) {
                vk[k] += __shfl_xor_sync(0xffffffffu, vk[k], 1);
                vk[k] += __shfl_xor_sync(0xffffffffu, vk[k], 2);
                vk[k] += __shfl_xor_sync(0xffffffffu, vk[k], 4);
            }
            if (seg == 0) {
                const int u = (hh < 2) ? hh : hh + 128;
                #pragma unroll
                for (int k = 0; k < 5; k++) smQ[u * 8 + k] = vk[k];
            }
        }

        // ---- fp16 k-loop: 64t x 32o per warp (+ q columns on wo==3) ----
        const uint32_t* hE = (const uint32_t*)(sm + (buf ? OFF_E1 : OFF_E0));
        float acc[4][4][4];
        float accq[4][4];
        #pragma unroll
        for (int mb = 0; mb < 4; mb++) {
            #pragma unroll
            for (int nb = 0; nb < 4; nb++)
                #pragma unroll
                for (int j = 0; j < 4; j++) acc[mb][nb][j] = 0.f;
            #pragma unroll
            for (int j = 0; j < 4; j++) accq[mb][j] = 0.f;
        }

        #pragma unroll
        for (int kb = 0; kb < 8; kb++) {
            const int kc = kb * 8;
            uint32_t b0[4], b1[4], bq0 = 0, bq1 = 0;
            #pragma unroll
            for (int nb = 0; nb < 4; nb++) {
                b0[nb] = hW[bBase + nb * 8 * STU + kc];
                b1[nb] = hW[bBase + nb * 8 * STU + kc + 4];
            }
            if (wo == 3) {
                bq0 = hW[bqBase + kc];
                bq1 = hW[bqBase + kc + 4];
            }
            #pragma unroll
            for (int mb = 0; mb < 4; mb++) {
                const int ao = aBase + mb * 16 * STU + kc;
                const uint32_t a0 = hE[ao];
                const uint32_t a1 = hE[ao + 8 * STU];
                const uint32_t a2 = hE[ao + 4];
                const uint32_t a3 = hE[ao + 8 * STU + 4];
                #pragma unroll
                for (int nb = 0; nb < 4; nb++)
                    mma16(acc[mb][nb], a0, a1, a2, a3, b0[nb], b1[nb]);
                if (wo == 3)
                    mma16(accq[mb], a0, a1, a2, a3, bq0, bq1);
            }
        }

        // ---- wo==3: scatter q fragments (cols j = 2lm, 2lm+1; keep j < 5) ----
        if (wo == 3 && lm < 3) {
            #pragma unroll
            for (int mb = 0; mb < 4; mb++) {
                const int u0 = mh * 64 + mb * 16 + l4 + 2;
                const int j0 = 2 * lm;
                smQ[u0 * 8 + j0] = accq[mb][0];
                smQ[(u0 + 8) * 8 + j0] = accq[mb][2];
                if (j0 + 1 < 5) {
                    smQ[u0 * 8 + j0 + 1] = accq[mb][1];
                    smQ[(u0 + 8) * 8 + j0 + 1] = accq[mb][3];
                }
            }
        }
        __syncthreads();   // q complete; E[buf] reads done

        // ---- sigmoid: s[t] = sum_k q[t+k][k] ----
        if (tid < 128) {
            float s = smQ[tid * 8]
                    + smQ[(tid + 1) * 8 + 1]
                    + smQ[(tid + 2) * 8 + 2]
                    + smQ[(tid + 3) * 8 + 3]
                    + smQ[(tid + 4) * 8 + 4];
            smSIG[tid] = 1.f / (1.f + __expf(-(s + bias)));
        }
        __syncthreads();

        // ---- epilogue: sigma_t * D, max over t, lane-reduce, store partials ----
        float vm[4][2];
        #pragma unroll
        for (int nb = 0; nb < 4; nb++) { vm[nb][0] = -INFINITY; vm[nb][1] = -INFINITY; }
        #pragma unroll
        for (int mb = 0; mb < 4; mb++) {
            const float s0 = smSIG[mh * 64 + mb * 16 + l4];
            const float s1 = smSIG[mh * 64 + mb * 16 + l4 + 8];
            #pragma unroll
            for (int nb = 0; nb < 4; nb++) {
                vm[nb][0] = fmaxf(vm[nb][0], fmaxf(s0 * acc[mb][nb][0], s1 * acc[mb][nb][2]));
                vm[nb][1] = fmaxf(vm[nb][1], fmaxf(s0 * acc[mb][nb][1], s1 * acc[mb][nb][3]));
            }
        }
        #pragma unroll
        for (int nb = 0; nb < 4; nb++) {
            #pragma unroll
            for (int j = 0; j < 2; j++) {
                float v = vm[nb][j];
                v = fmaxf(v, __shfl_xor_sync(0xffffffffu, v, 4));
                v = fmaxf(v, __shfl_xor_sync(0xffffffffu, v, 8));
                v = fmaxf(v, __shfl_xor_sync(0xffffffffu, v, 16));
                vm[nb][j] = v;
            }
        }
        if (l4 == 0) {   // lanes 0..3
            float* gp = g_part + (size_t)tile * 256 + mh * 128;
            #pragma unroll
            for (int nb = 0; nb < 4; nb++) {
                const int o = wo * 32 + nb * 8 + 2 * lane;
                gp[o]     = vm[nb][0];
                gp[o + 1] = vm[nb][1];
            }
        }
        buf ^= 1;
    }
}

__global__ void la_fin(const float* __restrict__ cnnb, float* __restrict__ out) {
    const int i = blockIdx.x * blockDim.x + threadIdx.x;   // b*128 + o
    const int b = i >> 7, o = i & 127;
    float m = -INFINITY;
    #pragma unroll
    for (int j = 0; j < 32; j++)
        m = fmaxf(m, g_part[((size_t)b * 32 + j) * 128 + o]);
    out[i] = tanhf(m + cnnb[o]);
}

extern "C" void kernel_launch(void* const* d_in, const int* in_sizes, int n_in,
                              void* d_out, int out_size) {
    const int*   x    = (const int*)d_in[0];
    const float* emb  = (const float*)d_in[1];
    const float* attw = (const float*)d_in[2];
    const float* attb = (const float*)d_in[3];
    const float* cnnw = (const float*)d_in[4];
    const float* cnnb = (const float*)d_in[5];
    float*       out  = (float*)d_out;

    emb_conv<<<(VOC1 * EE / 8 + 255) / 256, 256>>>(emb);
    cudaFuncSetAttribute(la_main, cudaFuncAttributeMaxDynamicSharedMemorySize, SMEM_DYN);
    la_main<<<GRID, 256, SMEM_DYN>>>(x, attw, attb, cnnw);
    la_fin<<<(BB * OCC) / 256, 256>>>(cnnb, out);
}